// round 9
// baseline (speedup 1.0000x reference)
#include <cuda_runtime.h>
#include <math.h>

// SpectralCirculantLayer: y = ifft(fft(x) * H) + bias, N=4096 per row, B=8192.
// rfft-4096 via c2c-2048 (even/odd pack), spectral multiply on bins 0..1023 (H
// truncated), one-sided inverse pack, irfft via c2c-2048.
// NEW DESIGN POINT (occupancy over stage count): radix 8*8*8*4 Stockham,
// 256 threads per row, ONE row per CTA, 8 points/thread -> ~57 regs ->
// __launch_bounds__(256,4) gives 4 CTAs/SM (32 warps) vs the 16x16x8
// kernel's register-bound 2 CTAs. Trades +33% smem traffic for 2x latency
// hiding. Global load fused into fwd stage 1, global store (+bias) fused
// into inv stage 4. Serial register twiddle chains, separate midstage.

#define NTHREADS 256
#define SB8 2304   // 2048 + 2048/8 padding

__device__ __forceinline__ int pd(int i) { return i + (i >> 3); }

__device__ __forceinline__ float2 cadd(float2 a, float2 b) { return make_float2(a.x + b.x, a.y + b.y); }
__device__ __forceinline__ float2 csub(float2 a, float2 b) { return make_float2(a.x - b.x, a.y - b.y); }
__device__ __forceinline__ float2 cmul(float2 a, float2 b) {
    return make_float2(fmaf(a.x, b.x, -a.y * b.y), fmaf(a.x, b.y, a.y * b.x));
}
__device__ __forceinline__ float2 conjf2(float2 a) { return make_float2(a.x, -a.y); }

template <int DIR>
__device__ __forceinline__ float2 mulJ(float2 a) {
    return (DIR < 0) ? make_float2(a.y, -a.x) : make_float2(-a.y, a.x);
}

template <int DIR>
__device__ __forceinline__ void dft4(float2* v) {
    float2 s0 = cadd(v[0], v[2]), d0 = csub(v[0], v[2]);
    float2 s1 = cadd(v[1], v[3]), d1 = mulJ<DIR>(csub(v[1], v[3]));
    v[0] = cadd(s0, s1);
    v[1] = cadd(d0, d1);
    v[2] = csub(s0, s1);
    v[3] = csub(d0, d1);
}

template <int DIR>
__device__ __forceinline__ void dft8(float2* v) {
    const float HC = 0.70710678118654752f;
    float2 b0 = cadd(v[0], v[4]);
    float2 b1 = cadd(v[1], v[5]);
    float2 b2 = cadd(v[2], v[6]);
    float2 b3 = cadd(v[3], v[7]);
    float2 c0 = csub(v[0], v[4]);
    float2 c1 = cmul(csub(v[1], v[5]), make_float2(HC, DIR * HC));
    float2 c2 = mulJ<DIR>(csub(v[2], v[6]));
    float2 c3 = cmul(csub(v[3], v[7]), make_float2(-HC, DIR * HC));
    {
        float2 s0 = cadd(b0, b2), d0 = csub(b0, b2);
        float2 s1 = cadd(b1, b3), d1 = mulJ<DIR>(csub(b1, b3));
        v[0] = cadd(s0, s1);
        v[2] = cadd(d0, d1);
        v[4] = csub(s0, s1);
        v[6] = csub(d0, d1);
    }
    {
        float2 s0 = cadd(c0, c2), d0 = csub(c0, c2);
        float2 s1 = cadd(c1, c3), d1 = mulJ<DIR>(csub(c1, c3));
        v[1] = cadd(s0, s1);
        v[3] = cadd(d0, d1);
        v[5] = csub(s0, s1);
        v[7] = csub(d0, d1);
    }
}

// Radix-8 Stockham stage. 256 butterflies, one per thread (t = 0..255).
// NS in {1, 8, 64}. GIN: stage 1 reads global (coalesced).
// Twiddle base wb = e^{DIR*2pi*i*(t mod NS)/(8*NS)}, serial power chain.
template <int DIR, int NS, int LOGNS, bool GIN>
__device__ __forceinline__ void stage8(const float2* __restrict__ in,
                                       float2* __restrict__ out, int t, float2 wb) {
    float2 v[8];
#pragma unroll
    for (int r = 0; r < 8; r++) v[r] = GIN ? in[t + (r << 8)] : in[pd(t + (r << 8))];
    if (NS > 1) {
        float2 wr = wb;
        v[1] = cmul(v[1], wr);
#pragma unroll
        for (int r = 2; r < 8; r++) {
            wr = cmul(wr, wb);
            v[r] = cmul(v[r], wr);
        }
    }
    dft8<DIR>(v);
    const int jm = t & (NS - 1);
    const int jd = t >> LOGNS;
    const int o = (jd << (LOGNS + 3)) + jm;
#pragma unroll
    for (int r = 0; r < 8; r++) out[pd(o + (r << LOGNS))] = v[r];
}

// Radix-4 final stage, NS=512: two butterflies per thread (j = t, t+256).
// Indices j + 512r on both sides. wA = e^{DIR*2pi*i*t/2048}, wB = wA*e^{DIR*pi*i/4}.
// GOUT: write global with bias (coalesced, unpadded).
template <int DIR, bool GOUT>
__device__ __forceinline__ void stage4_ns512(const float2* __restrict__ in,
                                             float2* __restrict__ out, int t,
                                             float2 wA, float2 wB, float bv) {
#pragma unroll
    for (int h = 0; h < 2; h++) {
        const int j = t + (h << 8);
        const float2 w = h ? wB : wA;
        float2 v[4];
#pragma unroll
        for (int r = 0; r < 4; r++) v[r] = in[pd(j + (r << 9))];
        float2 w2 = cmul(w, w);
        v[1] = cmul(v[1], w);
        v[2] = cmul(v[2], w2);
        v[3] = cmul(v[3], cmul(w2, w));
        dft4<DIR>(v);
#pragma unroll
        for (int r = 0; r < 4; r++) {
            if (GOUT)
                out[j + (r << 9)] = make_float2(v[r].x + bv, v[r].y + bv);
            else
                out[pd(j + (r << 9))] = v[r];
        }
    }
}

// Untangle rfft, multiply by H, repack one-sided for inverse.
// 256 threads, bins k = t + 256*i, i = 0..3. wqb = e^{-2pi*i*t/4096}.
__device__ __forceinline__ void midstage(const float2* __restrict__ S, float2* __restrict__ D,
                                         const float2* __restrict__ Hs, int t, float2 wqb) {
    // C[i] = e^{-pi*i*i/8}
    const float MCC[4] = {1.0f, 0.92387953251128675f, 0.70710678118654752f, 0.38268343236508977f};
    const float MCS[4] = {0.0f, -0.38268343236508977f, -0.70710678118654752f, -0.92387953251128675f};
#pragma unroll
    for (int i = 0; i < 4; i++) {
        const int k = t + (i << 8);
        const float2 wq = cmul(wqb, make_float2(MCC[i], MCS[i]));  // e^{-2pi*i*k/4096}
        float2 Zk = S[pd(k)];
        float2 Zm = S[pd((2048 - k) & 2047)];
        float2 E = make_float2(0.5f * (Zk.x + Zm.x), 0.5f * (Zk.y - Zm.y));
        float2 O = make_float2(0.5f * (Zk.y + Zm.y), -0.5f * (Zk.x - Zm.x));
        float2 Xk = cadd(E, cmul(O, wq));
        float2 Hk = Hs[k];
        float2 Yk = cmul(Xk, Hk);
        const float sc = 1.0f / 4096.0f;  // 0.5 (pack) * 1/2048 (IDFT)
        Yk.x *= sc;
        Yk.y *= sc;
        const float cph = wq.x, sph = -wq.y;
        D[pd(k)] = cmul(Yk, make_float2(1.0f - sph, cph));
        if (k > 0) {
            float2 Yc = make_float2(Yk.x, -Yk.y);
            D[pd(2048 - k)] = cmul(Yc, make_float2(1.0f + sph, cph));
        } else {
            D[pd(1024)] = make_float2(0.0f, 0.0f);
        }
    }
}

__global__ void __launch_bounds__(NTHREADS, 4)
spectral_circulant_kernel(const float* __restrict__ x, const float* __restrict__ wre,
                          const float* __restrict__ wim, const float* __restrict__ bias,
                          float* __restrict__ out, int nrows) {
    extern __shared__ float2 sm[];
    float2* A = sm;
    float2* B = sm + SB8;
    float2* Hs = sm + 2 * SB8;  // 1024 float2
    const int t = threadIdx.x;

    // One-time: cache H in smem
    for (int k = t; k < 1024; k += NTHREADS) Hs[k] = make_float2(__ldg(wre + k), __ldg(wim + k));
    const float bv = __ldg(bias);

    // Per-thread row-invariant twiddle bases
    float s, c;
    sincospif(-(float)(t & 7) * (1.0f / 32.0f), &s, &c);
    const float2 w2f = make_float2(c, s);  // e^{-2pi*i*(t&7)/64}
    sincospif(-(float)(t & 63) * (1.0f / 256.0f), &s, &c);
    const float2 w3f = make_float2(c, s);  // e^{-2pi*i*(t&63)/512}
    sincospif(-(float)t * (1.0f / 1024.0f), &s, &c);
    const float2 w4A = make_float2(c, s);  // e^{-2pi*i*t/2048}
    sincospif(-(float)t * (1.0f / 2048.0f), &s, &c);
    const float2 wqb = make_float2(c, s);  // e^{-2pi*i*t/4096}
    const float2 E4 = make_float2(0.70710678118654752f, -0.70710678118654752f);  // e^{-pi*i/4}
    const float2 w4B = cmul(w4A, E4);      // e^{-2pi*i*(t+256)/2048}
    const float2 w2i = conjf2(w2f);
    const float2 w3i = conjf2(w3f);
    const float2 w4Ai = conjf2(w4A);
    const float2 w4Bi = conjf2(w4B);
    __syncthreads();

    for (int row = blockIdx.x; row < nrows; row += gridDim.x) {
        const float2* xin = reinterpret_cast<const float2*>(x) + (size_t)row * 2048;
        float2* yout = reinterpret_cast<float2*>(out) + (size_t)row * 2048;

        // Forward c2c-2048: G -> A -> B -> A -> B
        stage8<-1, 1, 0, true>(xin, A, t, w2f);
        __syncthreads();
        stage8<-1, 8, 3, false>(A, B, t, w2f);
        __syncthreads();
        stage8<-1, 64, 6, false>(B, A, t, w3f);
        __syncthreads();
        stage4_ns512<-1, false>(A, B, t, w4A, w4B, 0.0f);
        __syncthreads();

        // Mid: B -> A
        midstage(B, A, Hs, t, wqb);
        __syncthreads();

        // Inverse c2c-2048: A -> B -> A -> B -> G
        stage8<1, 1, 0, false>(A, B, t, w2i);
        __syncthreads();
        stage8<1, 8, 3, false>(B, A, t, w2i);
        __syncthreads();
        stage8<1, 64, 6, false>(A, B, t, w3i);
        __syncthreads();
        stage4_ns512<1, true>(B, yout, t, w4Ai, w4Bi, bv);
        // no trailing sync: next row's stage 1 writes A, last read of A was
        // inv stage 3 which is followed by a __syncthreads.
    }
}

extern "C" void kernel_launch(void* const* d_in, const int* in_sizes, int n_in,
                              void* d_out, int out_size) {
    const float* x = (const float*)d_in[0];
    const float* wre = (const float*)d_in[1];
    const float* wim = (const float*)d_in[2];
    const float* bias = (const float*)d_in[3];
    float* out = (float*)d_out;

    const int nrows = in_sizes[0] / 4096;  // 8192
    const int smem_bytes = (2 * SB8 + 1024) * sizeof(float2);  // 45056

    static int grid = 0;
    if (grid == 0) {
        cudaFuncSetAttribute(spectral_circulant_kernel,
                             cudaFuncAttributeMaxDynamicSharedMemorySize, smem_bytes);
        int nsm = 148;
        cudaDeviceGetAttribute(&nsm, cudaDevAttrMultiProcessorCount, 0);
        grid = 4 * nsm;  // persistent, 4 CTAs/SM
    }

    spectral_circulant_kernel<<<grid, NTHREADS, smem_bytes>>>(x, wre, wim, bias, out, nrows);
}

// round 10
// speedup vs baseline: 1.5038x; 1.5038x over previous
#include <cuda_runtime.h>
#include <math.h>

// SpectralCirculantLayer: y = ifft(fft(x) * H) + bias, N=4096 per row, B=8192.
// rfft-4096 via c2c-2048 (even/odd pack), spectral multiply on bins 0..1023 (H
// truncated), one-sided inverse pack, irfft via c2c-2048.
// Radix 16*16*8 Stockham (3 smem stages per direction - the L1-traffic-minimal
// design; radix-8's 4 stages hit the L1 wall at 84%). 128 threads per CTA,
// ONE row per CTA (was: 2 rows per 256-thread CTA). __launch_bounds__(128,4)
// keeps the 128-reg budget (no codegen change) while shrinking barrier scope
// to 4 warps and giving 4 independent row streams per SM.
// Global load fused into fwd stage 1, global store (+bias) fused into inv
// stage 3. Serial register twiddle chains, separate midstage.

#define NTHREADS 128
#define SB16 2176   // 2048 + 2048/16 padding

__device__ __forceinline__ int pd(int i) { return i + (i >> 4); }

__device__ __forceinline__ float2 cadd(float2 a, float2 b) { return make_float2(a.x + b.x, a.y + b.y); }
__device__ __forceinline__ float2 csub(float2 a, float2 b) { return make_float2(a.x - b.x, a.y - b.y); }
__device__ __forceinline__ float2 cmul(float2 a, float2 b) {
    return make_float2(fmaf(a.x, b.x, -a.y * b.y), fmaf(a.x, b.y, a.y * b.x));
}
__device__ __forceinline__ float2 conjf2(float2 a) { return make_float2(a.x, -a.y); }

template <int DIR>
__device__ __forceinline__ float2 mulJ(float2 a) {
    return (DIR < 0) ? make_float2(a.y, -a.x) : make_float2(-a.y, a.x);
}

template <int DIR>
__device__ __forceinline__ void dft4(float2* v) {
    float2 s0 = cadd(v[0], v[2]), d0 = csub(v[0], v[2]);
    float2 s1 = cadd(v[1], v[3]), d1 = mulJ<DIR>(csub(v[1], v[3]));
    v[0] = cadd(s0, s1);
    v[1] = cadd(d0, d1);
    v[2] = csub(s0, s1);
    v[3] = csub(d0, d1);
}

template <int DIR>
__device__ __forceinline__ void dft8(float2* v) {
    const float HC = 0.70710678118654752f;
    float2 b0 = cadd(v[0], v[4]);
    float2 b1 = cadd(v[1], v[5]);
    float2 b2 = cadd(v[2], v[6]);
    float2 b3 = cadd(v[3], v[7]);
    float2 c0 = csub(v[0], v[4]);
    float2 c1 = cmul(csub(v[1], v[5]), make_float2(HC, DIR * HC));
    float2 c2 = mulJ<DIR>(csub(v[2], v[6]));
    float2 c3 = cmul(csub(v[3], v[7]), make_float2(-HC, DIR * HC));
    {
        float2 s0 = cadd(b0, b2), d0 = csub(b0, b2);
        float2 s1 = cadd(b1, b3), d1 = mulJ<DIR>(csub(b1, b3));
        v[0] = cadd(s0, s1);
        v[2] = cadd(d0, d1);
        v[4] = csub(s0, s1);
        v[6] = csub(d0, d1);
    }
    {
        float2 s0 = cadd(c0, c2), d0 = csub(c0, c2);
        float2 s1 = cadd(c1, c3), d1 = mulJ<DIR>(csub(c1, c3));
        v[1] = cadd(s0, s1);
        v[3] = cadd(d0, d1);
        v[5] = csub(s0, s1);
        v[7] = csub(d0, d1);
    }
}

// 16-point DFT in registers: two radix-4 levels (Stockham, self-sorting).
template <int DIR>
__device__ __forceinline__ void dft16(float2* v) {
    const float C1 = 0.92387953251128675f;
    const float S1 = 0.38268343236508977f;
    const float H2 = 0.70710678118654752f;
    const float2 W1 = make_float2(C1, DIR * S1);
    const float2 W2 = make_float2(H2, DIR * H2);
    const float2 W3 = make_float2(S1, DIR * C1);
    const float2 W6 = make_float2(-H2, DIR * H2);
    const float2 W9 = make_float2(-C1, -DIR * S1);

    float2 u[16];
#pragma unroll
    for (int i = 0; i < 4; i++) {
        float2 a[4] = {v[i], v[i + 4], v[i + 8], v[i + 12]};
        dft4<DIR>(a);
        u[4 * i + 0] = a[0];
        u[4 * i + 1] = a[1];
        u[4 * i + 2] = a[2];
        u[4 * i + 3] = a[3];
    }
    {
        float2 a[4] = {u[0], u[4], u[8], u[12]};
        dft4<DIR>(a);
        v[0] = a[0]; v[4] = a[1]; v[8] = a[2]; v[12] = a[3];
    }
    {
        float2 a[4] = {u[1], cmul(u[5], W1), cmul(u[9], W2), cmul(u[13], W3)};
        dft4<DIR>(a);
        v[1] = a[0]; v[5] = a[1]; v[9] = a[2]; v[13] = a[3];
    }
    {
        float2 a[4] = {u[2], cmul(u[6], W2), mulJ<DIR>(u[10]), cmul(u[14], W6)};
        dft4<DIR>(a);
        v[2] = a[0]; v[6] = a[1]; v[10] = a[2]; v[14] = a[3];
    }
    {
        float2 a[4] = {u[3], cmul(u[7], W3), cmul(u[11], W6), cmul(u[15], W9)};
        dft4<DIR>(a);
        v[3] = a[0]; v[7] = a[1]; v[11] = a[2]; v[15] = a[3];
    }
}

// Stage 1: radix-16, NS=1. tl = 0..127. Reads global (GIN) or padded smem.
template <int DIR, bool GIN>
__device__ __forceinline__ void stage_r16_ns1(const float2* __restrict__ in,
                                              float2* __restrict__ out, int tl) {
    float2 v[16];
#pragma unroll
    for (int r = 0; r < 16; r++) v[r] = GIN ? in[tl + (r << 7)] : in[pd(tl + (r << 7))];
    dft16<DIR>(v);
#pragma unroll
    for (int r = 0; r < 16; r++) out[pd((tl << 4) + r)] = v[r];
}

// Stage 2: radix-16, NS=16. Serial twiddle chain (low register liveness).
template <int DIR>
__device__ __forceinline__ void stage_r16_ns16(const float2* __restrict__ in,
                                               float2* __restrict__ out, int tl, float2 wb) {
    float2 v[16];
#pragma unroll
    for (int r = 0; r < 16; r++) v[r] = in[pd(tl + (r << 7))];
    float2 wr = wb;
    v[1] = cmul(v[1], wr);
#pragma unroll
    for (int r = 2; r < 16; r++) {
        wr = cmul(wr, wb);
        v[r] = cmul(v[r], wr);
    }
    dft16<DIR>(v);
    const int jm = tl & 15, jd = tl >> 4;
    const int o = (jd << 8) + jm;
#pragma unroll
    for (int r = 0; r < 16; r++) out[pd(o + (r << 4))] = v[r];
}

// Stage 3: radix-8, NS=256. Two butterflies per thread (j = tl, tl+128).
// GOUT: write to global with bias add (coalesced, unpadded).
template <int DIR, bool GOUT>
__device__ __forceinline__ void stage_r8_ns256(const float2* __restrict__ in,
                                               float2* __restrict__ out, int tl,
                                               float2 wA, float2 wB, float bv) {
#pragma unroll
    for (int h = 0; h < 2; h++) {
        const int j = tl + (h << 7);
        const float2 wb = h ? wB : wA;
        float2 v[8];
#pragma unroll
        for (int r = 0; r < 8; r++) v[r] = in[pd(j + (r << 8))];
        float2 wr = wb;
        v[1] = cmul(v[1], wr);
#pragma unroll
        for (int r = 2; r < 8; r++) {
            wr = cmul(wr, wb);
            v[r] = cmul(v[r], wr);
        }
        dft8<DIR>(v);
#pragma unroll
        for (int r = 0; r < 8; r++) {
            if (GOUT)
                out[j + (r << 8)] = make_float2(v[r].x + bv, v[r].y + bv);
            else
                out[pd(j + (r << 8))] = v[r];
        }
    }
}

// Untangle rfft, multiply by H, repack one-sided for inverse. wqb = e^{-2pi*i*tl/4096}.
__device__ __forceinline__ void midstage(const float2* __restrict__ S, float2* __restrict__ D,
                                         const float2* __restrict__ Hs, int tl, float2 wqb) {
    // MC[i] = e^{-pi*i*i/16}
    const float MCC[8] = {1.0f, 0.98078528040323044f, 0.92387953251128675f, 0.83146961230254524f,
                          0.70710678118654752f, 0.55557023301960222f, 0.38268343236508977f, 0.19509032201612827f};
    const float MCS[8] = {0.0f, -0.19509032201612827f, -0.38268343236508977f, -0.55557023301960222f,
                          -0.70710678118654752f, -0.83146961230254524f, -0.92387953251128675f, -0.98078528040323044f};
#pragma unroll
    for (int i = 0; i < 8; i++) {
        const int k = tl + (i << 7);
        const float2 wq = cmul(wqb, make_float2(MCC[i], MCS[i]));  // e^{-2pi*i*k/4096}
        float2 Zk = S[pd(k)];
        float2 Zm = S[pd((2048 - k) & 2047)];
        float2 E = make_float2(0.5f * (Zk.x + Zm.x), 0.5f * (Zk.y - Zm.y));
        float2 O = make_float2(0.5f * (Zk.y + Zm.y), -0.5f * (Zk.x - Zm.x));
        float2 Xk = cadd(E, cmul(O, wq));
        float2 Hk = Hs[k];
        float2 Yk = cmul(Xk, Hk);
        const float sc = 1.0f / 4096.0f;  // 0.5 (pack) * 1/2048 (IDFT)
        Yk.x *= sc;
        Yk.y *= sc;
        const float cph = wq.x, sph = -wq.y;
        D[pd(k)] = cmul(Yk, make_float2(1.0f - sph, cph));
        if (k > 0) {
            float2 Yc = make_float2(Yk.x, -Yk.y);
            D[pd(2048 - k)] = cmul(Yc, make_float2(1.0f + sph, cph));
        } else {
            D[pd(1024)] = make_float2(0.0f, 0.0f);
        }
    }
}

__global__ void __launch_bounds__(NTHREADS, 4)
spectral_circulant_kernel(const float* __restrict__ x, const float* __restrict__ wre,
                          const float* __restrict__ wim, const float* __restrict__ bias,
                          float* __restrict__ out, int nrows) {
    extern __shared__ float2 sm[];
    float2* X = sm;
    float2* Y = sm + SB16;
    float2* Hs = sm + 2 * SB16;  // 1024 float2
    const int tl = threadIdx.x;  // 0..127

    // One-time: cache H in smem
    for (int k = tl; k < 1024; k += NTHREADS) Hs[k] = make_float2(__ldg(wre + k), __ldg(wim + k));
    const float bv = __ldg(bias);

    // Per-thread twiddle bases (row-invariant)
    float s, c;
    sincospif(-(float)(tl & 15) * (1.0f / 128.0f), &s, &c);
    const float2 w2f = make_float2(c, s);  // e^{-2pi*i*(tl&15)/256}
    sincospif(-(float)tl * (1.0f / 1024.0f), &s, &c);
    const float2 w3f = make_float2(c, s);  // e^{-2pi*i*tl/2048}
    sincospif(-(float)tl * (1.0f / 2048.0f), &s, &c);
    const float2 wqb = make_float2(c, s);  // e^{-2pi*i*tl/4096}
    const float2 E8 = make_float2(0.92387953251128675f, -0.38268343236508977f);  // e^{-i*pi/8}
    const float2 w3g = cmul(w3f, E8);
    const float2 w2i = conjf2(w2f);
    const float2 w3i = conjf2(w3f);
    const float2 w3gi = conjf2(w3g);
    __syncthreads();  // Hs visible

    for (int row = blockIdx.x; row < nrows; row += gridDim.x) {
        const float2* xin = reinterpret_cast<const float2*>(x) + (size_t)row * 2048;
        float2* yout = reinterpret_cast<float2*>(out) + (size_t)row * 2048;

        // Forward c2c-2048: G -> Y -> X -> Y
        stage_r16_ns1<-1, true>(xin, Y, tl);
        __syncthreads();
        stage_r16_ns16<-1>(Y, X, tl, w2f);
        __syncthreads();
        stage_r8_ns256<-1, false>(X, Y, tl, w3f, w3g, 0.0f);
        __syncthreads();

        // Mid: Y -> X
        midstage(Y, X, Hs, tl, wqb);
        __syncthreads();

        // Inverse c2c-2048: X -> Y -> X -> G
        stage_r16_ns1<1, false>(X, Y, tl);
        __syncthreads();
        stage_r16_ns16<1>(Y, X, tl, w2i);
        __syncthreads();
        stage_r8_ns256<1, true>(X, yout, tl, w3i, w3gi, bv);
        // no trailing barrier: this stage's X reads precede the barrier after
        // the next row's stage 1 (which writes Y); X is next written only
        // after a later barrier.
    }
}

extern "C" void kernel_launch(void* const* d_in, const int* in_sizes, int n_in,
                              void* d_out, int out_size) {
    const float* x = (const float*)d_in[0];
    const float* wre = (const float*)d_in[1];
    const float* wim = (const float*)d_in[2];
    const float* bias = (const float*)d_in[3];
    float* out = (float*)d_out;

    const int nrows = in_sizes[0] / 4096;  // 8192
    const int smem_bytes = (2 * SB16 + 1024) * sizeof(float2);  // 43008

    static int grid = 0;
    if (grid == 0) {
        cudaFuncSetAttribute(spectral_circulant_kernel,
                             cudaFuncAttributeMaxDynamicSharedMemorySize, smem_bytes);
        int nsm = 148;
        cudaDeviceGetAttribute(&nsm, cudaDevAttrMultiProcessorCount, 0);
        grid = 4 * nsm;  // persistent, 4 CTAs/SM (1 row each)
    }

    spectral_circulant_kernel<<<grid, NTHREADS, smem_bytes>>>(x, wre, wim, bias, out, nrows);
}